// round 3
// baseline (speedup 1.0000x reference)
#include <cuda_runtime.h>

#define USER_NUM 100000
#define ITEM_NUM 50000
#define N_NODES  150000
#define EMB      64
#define TOT      (N_NODES * EMB)     /* 9,600,000 floats */
#define TOT4     (TOT / 4)           /* 2,400,000 float4 */

// Scratch (device globals — no allocation allowed in kernel_launch)
__device__ float g_ego[TOT];
__device__ float g_agg[TOT];
__device__ float g_t1[TOT];
__device__ float g_sum[TOT];

// ---------------------------------------------------------------------------
// init: ego = concat(user, item); sum = ego  (layer-0 term of the mean)
// ---------------------------------------------------------------------------
__global__ void init_kernel(const float4* __restrict__ user,
                            const float4* __restrict__ item) {
    int i = blockIdx.x * blockDim.x + threadIdx.x;
    if (i >= TOT4) return;
    const int U4 = USER_NUM * EMB / 4;
    float4 v = (i < U4) ? user[i] : item[i - U4];
    reinterpret_cast<float4*>(g_ego)[i] = v;
    reinterpret_cast<float4*>(g_sum)[i] = v;
}

__global__ void zero_agg_kernel() {
    int i = blockIdx.x * blockDim.x + threadIdx.x;
    if (i < TOT4)
        reinterpret_cast<float4*>(g_agg)[i] = make_float4(0.f, 0.f, 0.f, 0.f);
}

// ---------------------------------------------------------------------------
// SpMM: agg[r] += vals[e] * ego[c]   (COO, scattered fp32 vector reductions)
// 16 threads per edge, one float4 red per thread per vector.
// ---------------------------------------------------------------------------
__global__ void spmm_kernel(const int* __restrict__ rows,
                            const int* __restrict__ cols,
                            const float* __restrict__ vals, int nnz) {
    int gid = blockIdx.x * blockDim.x + threadIdx.x;
    int e = gid >> 4;
    if (e >= nnz) return;
    int t = gid & 15;

    int   r = __ldg(rows + e);
    int   c = __ldg(cols + e);
    float v = __ldg(vals + e);

    float4 x = reinterpret_cast<const float4*>(g_ego)[c * 16 + t];
    float* dst = g_agg + ((size_t)r * EMB + t * 4);
    asm volatile("red.global.add.v4.f32 [%0], {%1,%2,%3,%4};"
                 :: "l"(dst), "f"(v * x.x), "f"(v * x.y),
                    "f"(v * x.z), "f"(v * x.w)
                 : "memory");
}

// ---------------------------------------------------------------------------
// pass1: t1[row] = (ego[row] + agg[row]) @ W1
// thread-per-row, W1 staged in shared, row vector in registers
// ---------------------------------------------------------------------------
__global__ void __launch_bounds__(256)
pass1_kernel(const float* __restrict__ w1, int n) {
    __shared__ float ws[EMB * EMB];
    for (int i = threadIdx.x; i < EMB * EMB; i += blockDim.x) ws[i] = w1[i];
    __syncthreads();

    int row = blockIdx.x * blockDim.x + threadIdx.x;
    if (row >= n) return;

    float s[EMB];
    const float4* er = reinterpret_cast<const float4*>(g_ego) + row * 16;
    const float4* ar = reinterpret_cast<const float4*>(g_agg) + row * 16;
#pragma unroll
    for (int i = 0; i < 16; i++) {
        float4 a = er[i], b = ar[i];
        s[4*i+0] = a.x + b.x; s[4*i+1] = a.y + b.y;
        s[4*i+2] = a.z + b.z; s[4*i+3] = a.w + b.w;
    }

    float4* out = reinterpret_cast<float4*>(g_t1) + row * 16;
    for (int j = 0; j < 16; j++) {
        float4 acc = make_float4(0.f, 0.f, 0.f, 0.f);
#pragma unroll
        for (int i = 0; i < EMB; i++) {
            float4 w = reinterpret_cast<const float4*>(ws)[i * 16 + j];
            acc.x = fmaf(s[i], w.x, acc.x);
            acc.y = fmaf(s[i], w.y, acc.y);
            acc.z = fmaf(s[i], w.z, acc.z);
            acc.w = fmaf(s[i], w.w, acc.w);
        }
        out[j] = acc;
    }
}

// ---------------------------------------------------------------------------
// pass2: ego[row] = leaky_relu(t1[row] + (ego[row] * agg[row]) @ W2)
//        sum[row] += ego[row]
// ---------------------------------------------------------------------------
__global__ void __launch_bounds__(256)
pass2_kernel(const float* __restrict__ w2, int n) {
    __shared__ float ws[EMB * EMB];
    for (int i = threadIdx.x; i < EMB * EMB; i += blockDim.x) ws[i] = w2[i];
    __syncthreads();

    int row = blockIdx.x * blockDim.x + threadIdx.x;
    if (row >= n) return;

    float p[EMB];
    const float4* er = reinterpret_cast<const float4*>(g_ego) + row * 16;
    const float4* ar = reinterpret_cast<const float4*>(g_agg) + row * 16;
#pragma unroll
    for (int i = 0; i < 16; i++) {
        float4 a = er[i], b = ar[i];
        p[4*i+0] = a.x * b.x; p[4*i+1] = a.y * b.y;
        p[4*i+2] = a.z * b.z; p[4*i+3] = a.w * b.w;
    }

    const float4* t1r = reinterpret_cast<const float4*>(g_t1) + row * 16;
    float4* egow = reinterpret_cast<float4*>(g_ego) + row * 16;
    float4* sumw = reinterpret_cast<float4*>(g_sum) + row * 16;

    for (int j = 0; j < 16; j++) {
        float4 acc = t1r[j];
#pragma unroll
        for (int i = 0; i < EMB; i++) {
            float4 w = reinterpret_cast<const float4*>(ws)[i * 16 + j];
            acc.x = fmaf(p[i], w.x, acc.x);
            acc.y = fmaf(p[i], w.y, acc.y);
            acc.z = fmaf(p[i], w.z, acc.z);
            acc.w = fmaf(p[i], w.w, acc.w);
        }
        // leaky_relu (slope 0.01, jax.nn.leaky_relu default)
        acc.x = acc.x > 0.f ? acc.x : 0.01f * acc.x;
        acc.y = acc.y > 0.f ? acc.y : 0.01f * acc.y;
        acc.z = acc.z > 0.f ? acc.z : 0.01f * acc.z;
        acc.w = acc.w > 0.f ? acc.w : 0.01f * acc.w;

        egow[j] = acc;
        float4 sv = sumw[j];
        sv.x += acc.x; sv.y += acc.y; sv.z += acc.z; sv.w += acc.w;
        sumw[j] = sv;
    }
}

// ---------------------------------------------------------------------------
// final: out = sum / 4   (mean over 4 stacked embeddings)
// ---------------------------------------------------------------------------
__global__ void final_kernel(float4* __restrict__ out) {
    int i = blockIdx.x * blockDim.x + threadIdx.x;
    if (i >= TOT4) return;
    float4 v = reinterpret_cast<const float4*>(g_sum)[i];
    v.x *= 0.25f; v.y *= 0.25f; v.z *= 0.25f; v.w *= 0.25f;
    out[i] = v;
}

// ---------------------------------------------------------------------------
extern "C" void kernel_launch(void* const* d_in, const int* in_sizes, int n_in,
                              void* d_out, int out_size) {
    const float* user = (const float*)d_in[0];
    const float* item = (const float*)d_in[1];
    const float* w1   = (const float*)d_in[2];
    const float* w2   = (const float*)d_in[3];
    const float* vals = (const float*)d_in[4];
    const int*   rows = (const int*)d_in[5];
    const int*   cols = (const int*)d_in[6];
    int nnz = in_sizes[4];

    const int gv = (TOT4 + 255) / 256;           // vector-wide grids
    const int gs = (nnz * 16 + 255) / 256;       // spmm grid (16 thr/edge)
    const int gr = (N_NODES + 255) / 256;        // row-wide grids

    init_kernel<<<gv, 256>>>((const float4*)user, (const float4*)item);

    for (int k = 0; k < 3; k++) {
        zero_agg_kernel<<<gv, 256>>>();
        spmm_kernel<<<gs, 256>>>(rows, cols, vals, nnz);
        pass1_kernel<<<gr, 256>>>(w1 + k * EMB * EMB, N_NODES);
        pass2_kernel<<<gr, 256>>>(w2 + k * EMB * EMB, N_NODES);
    }

    final_kernel<<<gv, 256>>>((float4*)d_out);
}

// round 4
// speedup vs baseline: 1.4952x; 1.4952x over previous
#include <cuda_runtime.h>

#define USER_NUM 100000
#define ITEM_NUM 50000
#define N_NODES  150000
#define EMB      64
#define TOT      (N_NODES * EMB)
#define TOT4     (TOT / 4)
#define NNZ_MAX  2400000
#define NSCAN_BLK ((N_NODES + 255) / 256)   /* 586 */

// Scratch (device globals)
__device__ float g_ego[TOT];
__device__ float g_agg[TOT];
__device__ float g_sum[TOT];
__device__ int   g_cnt[N_NODES];
__device__ int   g_rowptr[N_NODES + 1];
__device__ int   g_cursor[N_NODES];
__device__ int   g_blksum[NSCAN_BLK];
__device__ int   g_cols[NNZ_MAX];
__device__ float g_vals[NNZ_MAX];

// ---------------------------------------------------------------------------
// init: ego = concat(user,item); sum = ego; also zero the CSR histogram
// ---------------------------------------------------------------------------
__global__ void init_kernel(const float4* __restrict__ user,
                            const float4* __restrict__ item) {
    int i = blockIdx.x * blockDim.x + threadIdx.x;
    if (i < N_NODES) g_cnt[i] = 0;
    if (i >= TOT4) return;
    const int U4 = USER_NUM * EMB / 4;
    float4 v = (i < U4) ? user[i] : item[i - U4];
    reinterpret_cast<float4*>(g_ego)[i] = v;
    reinterpret_cast<float4*>(g_sum)[i] = v;
}

// ---------------------------------------------------------------------------
// CSR build: histogram -> 2-level scan -> scatter
// ---------------------------------------------------------------------------
__global__ void hist_kernel(const int* __restrict__ rows, int nnz) {
    int e = blockIdx.x * blockDim.x + threadIdx.x;
    if (e < nnz) atomicAdd(&g_cnt[rows[e]], 1);
}

__global__ void scan1_kernel() {
    __shared__ int sh[256];
    int t = threadIdx.x;
    int sid = blockIdx.x * 256 + t;
    int v = (sid < N_NODES) ? g_cnt[sid] : 0;
    sh[t] = v;
    __syncthreads();
#pragma unroll
    for (int off = 1; off < 256; off <<= 1) {
        int x = (t >= off) ? sh[t - off] : 0;
        __syncthreads();
        sh[t] += x;
        __syncthreads();
    }
    if (sid < N_NODES) g_rowptr[sid] = sh[t] - v;   // exclusive within block
    if (t == 255) g_blksum[blockIdx.x] = sh[255];
}

__global__ void scan2_kernel() {
    __shared__ int sh[1024];
    int t = threadIdx.x;
    int v = (t < NSCAN_BLK) ? g_blksum[t] : 0;
    sh[t] = v;
    __syncthreads();
#pragma unroll
    for (int off = 1; off < 1024; off <<= 1) {
        int x = (t >= off) ? sh[t - off] : 0;
        __syncthreads();
        sh[t] += x;
        __syncthreads();
    }
    if (t < NSCAN_BLK) g_blksum[t] = sh[t] - v;     // exclusive block offsets
}

__global__ void scan3_kernel(int nnz) {
    int sid = blockIdx.x * blockDim.x + threadIdx.x;
    if (sid >= N_NODES) return;
    int rp = g_rowptr[sid] + g_blksum[sid >> 8];
    g_rowptr[sid] = rp;
    g_cursor[sid] = rp;
    if (sid == 0) g_rowptr[N_NODES] = nnz;
}

__global__ void scatter_kernel(const int* __restrict__ rows,
                               const int* __restrict__ cols,
                               const float* __restrict__ vals, int nnz) {
    int e = blockIdx.x * blockDim.x + threadIdx.x;
    if (e >= nnz) return;
    int r = rows[e];
    int pos = atomicAdd(&g_cursor[r], 1);
    g_cols[pos] = cols[e];
    g_vals[pos] = vals[e];
}

// ---------------------------------------------------------------------------
// Gather SpMM: agg[row] = sum_e vals[e] * ego[cols[e]]   (no atomics)
// 16 threads per row, each owns one float4 chunk, register accumulate.
// ---------------------------------------------------------------------------
__global__ void __launch_bounds__(256)
spmm_gather_kernel() {
    int gid = blockIdx.x * blockDim.x + threadIdx.x;
    int row = gid >> 4;
    if (row >= N_NODES) return;
    int t = gid & 15;

    int s0 = g_rowptr[row];
    int e0 = g_rowptr[row + 1];

    float4 acc = make_float4(0.f, 0.f, 0.f, 0.f);
    const float4* ego4 = reinterpret_cast<const float4*>(g_ego);
    for (int i = s0; i < e0; i++) {
        int   c = __ldg(g_cols + i);
        float v = __ldg(g_vals + i);
        float4 x = ego4[c * 16 + t];
        acc.x = fmaf(v, x.x, acc.x);
        acc.y = fmaf(v, x.y, acc.y);
        acc.z = fmaf(v, x.z, acc.z);
        acc.w = fmaf(v, x.w, acc.w);
    }
    reinterpret_cast<float4*>(g_agg)[row * 16 + t] = acc;
}

// ---------------------------------------------------------------------------
// Fused dense: ego = leaky_relu((ego+agg)@W1 + (ego*agg)@W2); sum += ego
// thread-per-row, W1 and W2 staged in shared, 2 float4 accumulators (8 chains)
// ---------------------------------------------------------------------------
__global__ void __launch_bounds__(128, 3)
fused_dense_kernel(const float* __restrict__ w1,
                   const float* __restrict__ w2, int n) {
    __shared__ float ws1[EMB * EMB];
    __shared__ float ws2[EMB * EMB];
    for (int i = threadIdx.x; i < EMB * EMB; i += blockDim.x) {
        ws1[i] = w1[i];
        ws2[i] = w2[i];
    }
    __syncthreads();

    int row = blockIdx.x * blockDim.x + threadIdx.x;
    if (row >= n) return;

    float s[EMB], p[EMB];
    const float4* er = reinterpret_cast<const float4*>(g_ego) + row * 16;
    const float4* ar = reinterpret_cast<const float4*>(g_agg) + row * 16;
#pragma unroll
    for (int i = 0; i < 16; i++) {
        float4 a = er[i], b = ar[i];
        s[4*i+0] = a.x + b.x; s[4*i+1] = a.y + b.y;
        s[4*i+2] = a.z + b.z; s[4*i+3] = a.w + b.w;
        p[4*i+0] = a.x * b.x; p[4*i+1] = a.y * b.y;
        p[4*i+2] = a.z * b.z; p[4*i+3] = a.w * b.w;
    }

    float4* egow = reinterpret_cast<float4*>(g_ego) + row * 16;
    float4* sumw = reinterpret_cast<float4*>(g_sum) + row * 16;
    const float4* w1v = reinterpret_cast<const float4*>(ws1);
    const float4* w2v = reinterpret_cast<const float4*>(ws2);

    for (int j = 0; j < 16; j += 2) {
        float4 a0 = make_float4(0.f, 0.f, 0.f, 0.f);
        float4 a1 = make_float4(0.f, 0.f, 0.f, 0.f);
#pragma unroll
        for (int i = 0; i < EMB; i++) {
            float4 wa0 = w1v[i * 16 + j];
            float4 wa1 = w1v[i * 16 + j + 1];
            float4 wb0 = w2v[i * 16 + j];
            float4 wb1 = w2v[i * 16 + j + 1];
            float si = s[i], pi = p[i];
            a0.x = fmaf(si, wa0.x, a0.x); a0.y = fmaf(si, wa0.y, a0.y);
            a0.z = fmaf(si, wa0.z, a0.z); a0.w = fmaf(si, wa0.w, a0.w);
            a1.x = fmaf(si, wa1.x, a1.x); a1.y = fmaf(si, wa1.y, a1.y);
            a1.z = fmaf(si, wa1.z, a1.z); a1.w = fmaf(si, wa1.w, a1.w);
            a0.x = fmaf(pi, wb0.x, a0.x); a0.y = fmaf(pi, wb0.y, a0.y);
            a0.z = fmaf(pi, wb0.z, a0.z); a0.w = fmaf(pi, wb0.w, a0.w);
            a1.x = fmaf(pi, wb1.x, a1.x); a1.y = fmaf(pi, wb1.y, a1.y);
            a1.z = fmaf(pi, wb1.z, a1.z); a1.w = fmaf(pi, wb1.w, a1.w);
        }
        // leaky_relu, slope 0.01
        a0.x = a0.x > 0.f ? a0.x : 0.01f * a0.x;
        a0.y = a0.y > 0.f ? a0.y : 0.01f * a0.y;
        a0.z = a0.z > 0.f ? a0.z : 0.01f * a0.z;
        a0.w = a0.w > 0.f ? a0.w : 0.01f * a0.w;
        a1.x = a1.x > 0.f ? a1.x : 0.01f * a1.x;
        a1.y = a1.y > 0.f ? a1.y : 0.01f * a1.y;
        a1.z = a1.z > 0.f ? a1.z : 0.01f * a1.z;
        a1.w = a1.w > 0.f ? a1.w : 0.01f * a1.w;

        egow[j] = a0;
        egow[j + 1] = a1;
        float4 s0v = sumw[j], s1v = sumw[j + 1];
        s0v.x += a0.x; s0v.y += a0.y; s0v.z += a0.z; s0v.w += a0.w;
        s1v.x += a1.x; s1v.y += a1.y; s1v.z += a1.z; s1v.w += a1.w;
        sumw[j] = s0v;
        sumw[j + 1] = s1v;
    }
}

// ---------------------------------------------------------------------------
// final: out = sum / 4
// ---------------------------------------------------------------------------
__global__ void final_kernel(float4* __restrict__ out) {
    int i = blockIdx.x * blockDim.x + threadIdx.x;
    if (i >= TOT4) return;
    float4 v = reinterpret_cast<const float4*>(g_sum)[i];
    v.x *= 0.25f; v.y *= 0.25f; v.z *= 0.25f; v.w *= 0.25f;
    out[i] = v;
}

// ---------------------------------------------------------------------------
extern "C" void kernel_launch(void* const* d_in, const int* in_sizes, int n_in,
                              void* d_out, int out_size) {
    const float* user = (const float*)d_in[0];
    const float* item = (const float*)d_in[1];
    const float* w1   = (const float*)d_in[2];
    const float* w2   = (const float*)d_in[3];
    const float* vals = (const float*)d_in[4];
    const int*   rows = (const int*)d_in[5];
    const int*   cols = (const int*)d_in[6];
    int nnz = in_sizes[4];
    if (nnz > NNZ_MAX) nnz = NNZ_MAX;

    const int gv  = (TOT4 + 255) / 256;
    const int ge  = (nnz + 255) / 256;
    const int gg  = (N_NODES * 16 + 255) / 256;
    const int gf  = (N_NODES + 127) / 128;

    init_kernel<<<gv, 256>>>((const float4*)user, (const float4*)item);

    // CSR build (once; reused by all 3 layers)
    hist_kernel<<<ge, 256>>>(rows, nnz);
    scan1_kernel<<<NSCAN_BLK, 256>>>();
    scan2_kernel<<<1, 1024>>>();
    scan3_kernel<<<NSCAN_BLK, 256>>>(nnz);
    scatter_kernel<<<ge, 256>>>(rows, cols, vals, nnz);

    for (int k = 0; k < 3; k++) {
        spmm_gather_kernel<<<gg, 256>>>();
        fused_dense_kernel<<<gf, 128>>>(w1 + k * EMB * EMB,
                                        w2 + k * EMB * EMB, N_NODES);
    }

    final_kernel<<<gv, 256>>>((float4*)d_out);
}

// round 6
// speedup vs baseline: 1.5944x; 1.0664x over previous
#include <cuda_runtime.h>

#define USER_NUM 100000
#define ITEM_NUM 50000
#define N_NODES  150000
#define EMB      64
#define TOT      (N_NODES * EMB)
#define TOT4     (TOT / 4)
#define NNZ_MAX  2400000
#define NSCAN_BLK ((N_NODES + 255) / 256)   /* 586 */
#define NTILE32   ((N_NODES + 31) / 32)     /* 4688 */
#define FUSED_GRID 592                      /* 148 SMs x 4 blocks */

// Scratch (device globals)
__device__ float g_egoA[TOT];
__device__ float g_egoB[TOT];
__device__ float g_sum[TOT];
__device__ int   g_cnt[N_NODES];
__device__ int   g_rowptr[N_NODES + 1];
__device__ int   g_cursor[N_NODES];
__device__ int   g_blksum[NSCAN_BLK];
__device__ int   g_cols[NNZ_MAX];
__device__ float g_vals[NNZ_MAX];

// ---------------------------------------------------------------------------
// init: egoA = concat(user,item); sum = egoA; zero CSR histogram
// ---------------------------------------------------------------------------
__global__ void init_kernel(const float4* __restrict__ user,
                            const float4* __restrict__ item) {
    int i = blockIdx.x * blockDim.x + threadIdx.x;
    if (i < N_NODES) g_cnt[i] = 0;
    if (i >= TOT4) return;
    const int U4 = USER_NUM * EMB / 4;
    float4 v = (i < U4) ? user[i] : item[i - U4];
    reinterpret_cast<float4*>(g_egoA)[i] = v;
    reinterpret_cast<float4*>(g_sum)[i] = v;
}

// ---------------------------------------------------------------------------
// CSR build: histogram -> 2-level scan -> scatter
// ---------------------------------------------------------------------------
__global__ void hist_kernel(const int* __restrict__ rows, int nnz) {
    int e = blockIdx.x * blockDim.x + threadIdx.x;
    if (e < nnz) atomicAdd(&g_cnt[rows[e]], 1);
}

__global__ void scan1_kernel() {
    __shared__ int sh[256];
    int t = threadIdx.x;
    int sid = blockIdx.x * 256 + t;
    int v = (sid < N_NODES) ? g_cnt[sid] : 0;
    sh[t] = v;
    __syncthreads();
#pragma unroll
    for (int off = 1; off < 256; off <<= 1) {
        int x = (t >= off) ? sh[t - off] : 0;
        __syncthreads();
        sh[t] += x;
        __syncthreads();
    }
    if (sid < N_NODES) g_rowptr[sid] = sh[t] - v;   // exclusive within block
    if (t == 255) g_blksum[blockIdx.x] = sh[255];
}

__global__ void scan2_kernel() {
    __shared__ int sh[1024];
    int t = threadIdx.x;
    int v = (t < NSCAN_BLK) ? g_blksum[t] : 0;
    sh[t] = v;
    __syncthreads();
#pragma unroll
    for (int off = 1; off < 1024; off <<= 1) {
        int x = (t >= off) ? sh[t - off] : 0;
        __syncthreads();
        sh[t] += x;
        __syncthreads();
    }
    if (t < NSCAN_BLK) g_blksum[t] = sh[t] - v;     // exclusive block offsets
}

__global__ void scan3_kernel(int nnz) {
    int sid = blockIdx.x * blockDim.x + threadIdx.x;
    if (sid >= N_NODES) return;
    int rp = g_rowptr[sid] + g_blksum[sid >> 8];
    g_rowptr[sid] = rp;
    g_cursor[sid] = rp;
    if (sid == 0) g_rowptr[N_NODES] = nnz;
}

__global__ void scatter_kernel(const int* __restrict__ rows,
                               const int* __restrict__ cols,
                               const float* __restrict__ vals, int nnz) {
    int e = blockIdx.x * blockDim.x + threadIdx.x;
    if (e >= nnz) return;
    int r = rows[e];
    int pos = atomicAdd(&g_cursor[r], 1);
    g_cols[pos] = cols[e];
    g_vals[pos] = vals[e];
}

// ---------------------------------------------------------------------------
// Fused layer: persistent blocks, 32-row tiles.
//   agg  = A @ src                 (CSR gather, no atomics)
//   ego' = leaky((src+agg)@W1 + (src*agg)@W2)
//   sum += ego'   (or last layer: out = (sum+ego')*0.25)
// Each thread: gathers 2 rows' j-chunk, then GEMVs 2 rows reusing weight LDS.
// ---------------------------------------------------------------------------
__device__ __forceinline__ void gather_row(const float4* __restrict__ src,
                                           int row, int t, float4& acc) {
    int s0 = g_rowptr[row];
    int e0 = g_rowptr[row + 1];
    int i = s0;
    for (; i + 1 < e0; i += 2) {
        int   c0 = __ldg(g_cols + i);
        int   c1 = __ldg(g_cols + i + 1);
        float v0 = __ldg(g_vals + i);
        float v1 = __ldg(g_vals + i + 1);
        float4 x0 = src[c0 * 16 + t];
        float4 x1 = src[c1 * 16 + t];
        acc.x = fmaf(v0, x0.x, acc.x); acc.y = fmaf(v0, x0.y, acc.y);
        acc.z = fmaf(v0, x0.z, acc.z); acc.w = fmaf(v0, x0.w, acc.w);
        acc.x = fmaf(v1, x1.x, acc.x); acc.y = fmaf(v1, x1.y, acc.y);
        acc.z = fmaf(v1, x1.z, acc.z); acc.w = fmaf(v1, x1.w, acc.w);
    }
    if (i < e0) {
        int   c = __ldg(g_cols + i);
        float v = __ldg(g_vals + i);
        float4 x = src[c * 16 + t];
        acc.x = fmaf(v, x.x, acc.x); acc.y = fmaf(v, x.y, acc.y);
        acc.z = fmaf(v, x.z, acc.z); acc.w = fmaf(v, x.w, acc.w);
    }
}

__global__ void __launch_bounds__(256, 4)
fused_layer_kernel(const float4* __restrict__ src,
                   float4* __restrict__ dst,
                   const float4* __restrict__ w1,
                   const float4* __restrict__ w2,
                   int last, float4* __restrict__ out) {
    __shared__ float4 ws1[EMB * 16];         // 16KB: W1[i][4t..4t+3] at [i*16+t]
    __shared__ float4 ws2[EMB * 16];         // 16KB
    __shared__ float  ssh[32 * EMB];         // 8KB  (ego+agg, 32 rows)
    __shared__ float  psh[32 * EMB];         // 8KB  (ego*agg, 32 rows)

    for (int i = threadIdx.x; i < EMB * 16; i += 256) {
        ws1[i] = w1[i];
        ws2[i] = w2[i];
    }

    const int t  = threadIdx.x & 15;    // j-chunk: columns 4t..4t+3
    const int rl = threadIdx.x >> 4;    // 0..15 -> rows rl and rl+16 of tile

    for (int tile = blockIdx.x; tile < NTILE32; tile += gridDim.x) {
        __syncthreads();   // smem reuse guard (also orders first weight load)

        int rowA = tile * 32 + rl;
        int rowB = rowA + 16;
        bool vA = rowA < N_NODES;
        bool vB = rowB < N_NODES;

        float4 accA = make_float4(0.f, 0.f, 0.f, 0.f);
        float4 accB = make_float4(0.f, 0.f, 0.f, 0.f);
        if (vA) gather_row(src, rowA, t, accA);
        if (vB) gather_row(src, rowB, t, accB);

        if (vA) {
            float4 e = src[rowA * 16 + t];
            float4 s4, p4;
            s4.x = e.x + accA.x; s4.y = e.y + accA.y;
            s4.z = e.z + accA.z; s4.w = e.w + accA.w;
            p4.x = e.x * accA.x; p4.y = e.y * accA.y;
            p4.z = e.z * accA.z; p4.w = e.w * accA.w;
            *reinterpret_cast<float4*>(ssh + rl * EMB + 4 * t) = s4;
            *reinterpret_cast<float4*>(psh + rl * EMB + 4 * t) = p4;
        }
        if (vB) {
            float4 e = src[rowB * 16 + t];
            float4 s4, p4;
            s4.x = e.x + accB.x; s4.y = e.y + accB.y;
            s4.z = e.z + accB.z; s4.w = e.w + accB.w;
            p4.x = e.x * accB.x; p4.y = e.y * accB.y;
            p4.z = e.z * accB.z; p4.w = e.w * accB.w;
            *reinterpret_cast<float4*>(ssh + (rl + 16) * EMB + 4 * t) = s4;
            *reinterpret_cast<float4*>(psh + (rl + 16) * EMB + 4 * t) = p4;
        }
        __syncthreads();

        // GEMV: outputs 4t..4t+3 for rows rl (A) and rl+16 (B).
        // Each weight float4 is reused for 16 FMAs (2 rows x s & p x 4 lanes... 8 per row).
        float4 oA = make_float4(0.f, 0.f, 0.f, 0.f);
        float4 oB = make_float4(0.f, 0.f, 0.f, 0.f);
        const float* sA = ssh + rl * EMB;
        const float* pA = psh + rl * EMB;
        const float* sB = ssh + (rl + 16) * EMB;
        const float* pB = psh + (rl + 16) * EMB;

#pragma unroll
        for (int i4 = 0; i4 < 16; i4++) {
            float4 sa = *reinterpret_cast<const float4*>(sA + 4 * i4);
            float4 pa = *reinterpret_cast<const float4*>(pA + 4 * i4);
            float4 sb = *reinterpret_cast<const float4*>(sB + 4 * i4);
            float4 pb = *reinterpret_cast<const float4*>(pB + 4 * i4);

#define GEMV_STEP(u, SC, PC)                                                 \
            {                                                                \
                float4 wa = ws1[(i4 * 4 + u) * 16 + t];                      \
                float4 wb = ws2[(i4 * 4 + u) * 16 + t];                      \
                oA.x = fmaf(sa.SC, wa.x, oA.x); oA.y = fmaf(sa.SC, wa.y, oA.y); \
                oA.z = fmaf(sa.SC, wa.z, oA.z); oA.w = fmaf(sa.SC, wa.w, oA.w); \
                oA.x = fmaf(pa.PC, wb.x, oA.x); oA.y = fmaf(pa.PC, wb.y, oA.y); \
                oA.z = fmaf(pa.PC, wb.z, oA.z); oA.w = fmaf(pa.PC, wb.w, oA.w); \
                oB.x = fmaf(sb.SC, wa.x, oB.x); oB.y = fmaf(sb.SC, wa.y, oB.y); \
                oB.z = fmaf(sb.SC, wa.z, oB.z); oB.w = fmaf(sb.SC, wa.w, oB.w); \
                oB.x = fmaf(pb.PC, wb.x, oB.x); oB.y = fmaf(pb.PC, wb.y, oB.y); \
                oB.z = fmaf(pb.PC, wb.z, oB.z); oB.w = fmaf(pb.PC, wb.w, oB.w); \
            }
            GEMV_STEP(0, x, x)
            GEMV_STEP(1, y, y)
            GEMV_STEP(2, z, z)
            GEMV_STEP(3, w, w)
#undef GEMV_STEP
        }

        // leaky_relu slope 0.01
        oA.x = oA.x > 0.f ? oA.x : 0.01f * oA.x;
        oA.y = oA.y > 0.f ? oA.y : 0.01f * oA.y;
        oA.z = oA.z > 0.f ? oA.z : 0.01f * oA.z;
        oA.w = oA.w > 0.f ? oA.w : 0.01f * oA.w;
        oB.x = oB.x > 0.f ? oB.x : 0.01f * oB.x;
        oB.y = oB.y > 0.f ? oB.y : 0.01f * oB.y;
        oB.z = oB.z > 0.f ? oB.z : 0.01f * oB.z;
        oB.w = oB.w > 0.f ? oB.w : 0.01f * oB.w;

        if (!last) {
            if (vA) {
                dst[rowA * 16 + t] = oA;
                float4 sm = reinterpret_cast<const float4*>(g_sum)[rowA * 16 + t];
                sm.x += oA.x; sm.y += oA.y; sm.z += oA.z; sm.w += oA.w;
                reinterpret_cast<float4*>(g_sum)[rowA * 16 + t] = sm;
            }
            if (vB) {
                dst[rowB * 16 + t] = oB;
                float4 sm = reinterpret_cast<const float4*>(g_sum)[rowB * 16 + t];
                sm.x += oB.x; sm.y += oB.y; sm.z += oB.z; sm.w += oB.w;
                reinterpret_cast<float4*>(g_sum)[rowB * 16 + t] = sm;
            }
        } else {
            if (vA) {
                float4 sm = reinterpret_cast<const float4*>(g_sum)[rowA * 16 + t];
                sm.x = (sm.x + oA.x) * 0.25f; sm.y = (sm.y + oA.y) * 0.25f;
                sm.z = (sm.z + oA.z) * 0.25f; sm.w = (sm.w + oA.w) * 0.25f;
                out[rowA * 16 + t] = sm;
            }
            if (vB) {
                float4 sm = reinterpret_cast<const float4*>(g_sum)[rowB * 16 + t];
                sm.x = (sm.x + oB.x) * 0.25f; sm.y = (sm.y + oB.y) * 0.25f;
                sm.z = (sm.z + oB.z) * 0.25f; sm.w = (sm.w + oB.w) * 0.25f;
                out[rowB * 16 + t] = sm;
            }
        }
    }
}

// ---------------------------------------------------------------------------
extern "C" void kernel_launch(void* const* d_in, const int* in_sizes, int n_in,
                              void* d_out, int out_size) {
    const float* user = (const float*)d_in[0];
    const float* item = (const float*)d_in[1];
    const float* w1   = (const float*)d_in[2];
    const float* w2   = (const float*)d_in[3];
    const float* vals = (const float*)d_in[4];
    const int*   rows = (const int*)d_in[5];
    const int*   cols = (const int*)d_in[6];
    int nnz = in_sizes[4];
    if (nnz > NNZ_MAX) nnz = NNZ_MAX;

    const int gv = (TOT4 + 255) / 256;
    const int ge = (nnz + 255) / 256;

    init_kernel<<<gv, 256>>>((const float4*)user, (const float4*)item);

    // CSR build (once; reused by all 3 layers)
    hist_kernel<<<ge, 256>>>(rows, nnz);
    scan1_kernel<<<NSCAN_BLK, 256>>>();
    scan2_kernel<<<1, 1024>>>();
    scan3_kernel<<<NSCAN_BLK, 256>>>(nnz);
    scatter_kernel<<<ge, 256>>>(rows, cols, vals, nnz);

    float4* egoA = nullptr;
    float4* egoB = nullptr;
    cudaGetSymbolAddress((void**)&egoA, g_egoA);
    cudaGetSymbolAddress((void**)&egoB, g_egoB);

    const float4* w1v = (const float4*)w1;
    const float4* w2v = (const float4*)w2;

    // layer 0: A -> B, layer 1: B -> A, layer 2 (last): A -> out
    fused_layer_kernel<<<FUSED_GRID, 256>>>(egoA, egoB, w1v,        w2v,        0, nullptr);
    fused_layer_kernel<<<FUSED_GRID, 256>>>(egoB, egoA, w1v + 1024, w2v + 1024, 0, nullptr);
    fused_layer_kernel<<<FUSED_GRID, 256>>>(egoA, nullptr, w1v + 2048, w2v + 2048, 1,
                                            (float4*)d_out);
}

// round 9
// speedup vs baseline: 1.7414x; 1.0922x over previous
#include <cuda_runtime.h>

#define USER_NUM 100000
#define ITEM_NUM 50000
#define N_NODES  150000
#define EMB      64
#define TOT      (N_NODES * EMB)
#define TOT4     (TOT / 4)
#define NNZ_MAX  2400000
#define NSCAN_BLK ((N_NODES + 255) / 256)   /* 586 */
#define NTILE32   ((N_NODES + 31) / 32)     /* 4688 */
#define FUSED_GRID 592                      /* 148 SMs x 4 blocks */

typedef unsigned long long u64;

// ---------------- packed f32x2 helpers (FFMA2 et al., PTX-only) ------------
__device__ __forceinline__ u64 fma2(u64 a, u64 b, u64 c) {
    u64 d; asm("fma.rn.f32x2 %0, %1, %2, %3;" : "=l"(d) : "l"(a), "l"(b), "l"(c));
    return d;
}
__device__ __forceinline__ u64 add2(u64 a, u64 b) {
    u64 d; asm("add.rn.f32x2 %0, %1, %2;" : "=l"(d) : "l"(a), "l"(b));
    return d;
}
__device__ __forceinline__ u64 mul2(u64 a, u64 b) {
    u64 d; asm("mul.rn.f32x2 %0, %1, %2;" : "=l"(d) : "l"(a), "l"(b));
    return d;
}
__device__ __forceinline__ u64 dup2(float s) {
    u64 d; asm("mov.b64 %0, {%1, %1};" : "=l"(d) : "f"(s));
    return d;
}
__device__ __forceinline__ u64 pack2(float lo, float hi) {
    u64 d; asm("mov.b64 %0, {%1, %2};" : "=l"(d) : "f"(lo), "f"(hi));
    return d;
}
__device__ __forceinline__ float2 unpack2(u64 v) {
    float2 r; asm("mov.b64 {%0, %1}, %2;" : "=f"(r.x), "=f"(r.y) : "l"(v));
    return r;
}

// Scratch (device globals)
__device__ float g_egoA[TOT];
__device__ float g_egoB[TOT];
__device__ float g_sum[TOT];
__device__ int   g_cnt[N_NODES];
__device__ int   g_rowptr[N_NODES + 1];
__device__ int   g_cursor[N_NODES];
__device__ int   g_blksum[NSCAN_BLK];
__device__ int2  g_edge[NNZ_MAX];           // (col, val bits) packed

// ---------------------------------------------------------------------------
// init: egoA = concat(user,item); sum = egoA; zero CSR histogram
// ---------------------------------------------------------------------------
__global__ void init_kernel(const float4* __restrict__ user,
                            const float4* __restrict__ item) {
    int i = blockIdx.x * blockDim.x + threadIdx.x;
    if (i < N_NODES) g_cnt[i] = 0;
    if (i >= TOT4) return;
    const int U4 = USER_NUM * EMB / 4;
    float4 v = (i < U4) ? user[i] : item[i - U4];
    reinterpret_cast<float4*>(g_egoA)[i] = v;
    reinterpret_cast<float4*>(g_sum)[i] = v;
}

// ---------------------------------------------------------------------------
// CSR build: histogram -> 2-level scan -> scatter (col,val packed)
// ---------------------------------------------------------------------------
__global__ void hist_kernel(const int* __restrict__ rows, int nnz) {
    int e = blockIdx.x * blockDim.x + threadIdx.x;
    if (e < nnz) atomicAdd(&g_cnt[rows[e]], 1);
}

__global__ void scan1_kernel() {
    __shared__ int sh[256];
    int t = threadIdx.x;
    int sid = blockIdx.x * 256 + t;
    int v = (sid < N_NODES) ? g_cnt[sid] : 0;
    sh[t] = v;
    __syncthreads();
#pragma unroll
    for (int off = 1; off < 256; off <<= 1) {
        int x = (t >= off) ? sh[t - off] : 0;
        __syncthreads();
        sh[t] += x;
        __syncthreads();
    }
    if (sid < N_NODES) g_rowptr[sid] = sh[t] - v;
    if (t == 255) g_blksum[blockIdx.x] = sh[255];
}

__global__ void scan2_kernel() {
    __shared__ int sh[1024];
    int t = threadIdx.x;
    int v = (t < NSCAN_BLK) ? g_blksum[t] : 0;
    sh[t] = v;
    __syncthreads();
#pragma unroll
    for (int off = 1; off < 1024; off <<= 1) {
        int x = (t >= off) ? sh[t - off] : 0;
        __syncthreads();
        sh[t] += x;
        __syncthreads();
    }
    if (t < NSCAN_BLK) g_blksum[t] = sh[t] - v;
}

__global__ void scan3_kernel(int nnz) {
    int sid = blockIdx.x * blockDim.x + threadIdx.x;
    if (sid >= N_NODES) return;
    int rp = g_rowptr[sid] + g_blksum[sid >> 8];
    g_rowptr[sid] = rp;
    g_cursor[sid] = rp;
    if (sid == 0) g_rowptr[N_NODES] = nnz;
}

__global__ void scatter_kernel(const int* __restrict__ rows,
                               const int* __restrict__ cols,
                               const float* __restrict__ vals, int nnz) {
    int e = blockIdx.x * blockDim.x + threadIdx.x;
    if (e >= nnz) return;
    int r = rows[e];
    int pos = atomicAdd(&g_cursor[r], 1);
    g_edge[pos] = make_int2(cols[e], __float_as_int(vals[e]));
}

// ---------------------------------------------------------------------------
// CSR gather for one row's float4 chunk t, packed f32x2 accumulate.
// ---------------------------------------------------------------------------
__device__ __forceinline__ void gather_row(const ulonglong2* __restrict__ srcu,
                                           int row, int t, u64& a01, u64& a23) {
    int s0 = g_rowptr[row];
    int e0 = g_rowptr[row + 1];
    int i = s0;
    for (; i + 3 < e0; i += 4) {
        int2 m0 = __ldg(g_edge + i);
        int2 m1 = __ldg(g_edge + i + 1);
        int2 m2 = __ldg(g_edge + i + 2);
        int2 m3 = __ldg(g_edge + i + 3);
        ulonglong2 x0 = srcu[(size_t)m0.x * 16 + t];
        ulonglong2 x1 = srcu[(size_t)m1.x * 16 + t];
        ulonglong2 x2 = srcu[(size_t)m2.x * 16 + t];
        ulonglong2 x3 = srcu[(size_t)m3.x * 16 + t];
        u64 v0 = dup2(__int_as_float(m0.y));
        u64 v1 = dup2(__int_as_float(m1.y));
        u64 v2 = dup2(__int_as_float(m2.y));
        u64 v3 = dup2(__int_as_float(m3.y));
        a01 = fma2(v0, x0.x, a01); a23 = fma2(v0, x0.y, a23);
        a01 = fma2(v1, x1.x, a01); a23 = fma2(v1, x1.y, a23);
        a01 = fma2(v2, x2.x, a01); a23 = fma2(v2, x2.y, a23);
        a01 = fma2(v3, x3.x, a01); a23 = fma2(v3, x3.y, a23);
    }
    for (; i < e0; i++) {
        int2 m = __ldg(g_edge + i);
        ulonglong2 x = srcu[(size_t)m.x * 16 + t];
        u64 v = dup2(__int_as_float(m.y));
        a01 = fma2(v, x.x, a01); a23 = fma2(v, x.y, a23);
    }
}

// ---------------------------------------------------------------------------
// Fused layer: persistent blocks, 32-row tiles.
//   agg  = A @ src;  ego' = leaky((src+agg)@W1 + (src*agg)@W2)
//   sum += ego'  (last layer: out = (sum+ego')*0.25)
// ---------------------------------------------------------------------------
__global__ void __launch_bounds__(256, 4)
fused_layer_kernel(const float4* __restrict__ src,
                   float4* __restrict__ dst,
                   const float4* __restrict__ w1,
                   const float4* __restrict__ w2,
                   int last, float4* __restrict__ out) {
    __shared__ float4 ws1[EMB * 16];         // 16KB
    __shared__ float4 ws2[EMB * 16];         // 16KB
    __shared__ float  ssh[32 * EMB];         // 8KB  (ego+agg)
    __shared__ float  psh[32 * EMB];         // 8KB  (ego*agg)

    for (int i = threadIdx.x; i < EMB * 16; i += 256) {
        ws1[i] = w1[i];
        ws2[i] = w2[i];
    }

    const int t  = threadIdx.x & 15;
    const int rl = threadIdx.x >> 4;

    const ulonglong2* srcu = reinterpret_cast<const ulonglong2*>(src);
    const ulonglong2* w1u  = reinterpret_cast<const ulonglong2*>(ws1);
    const ulonglong2* w2u  = reinterpret_cast<const ulonglong2*>(ws2);

    for (int tile = blockIdx.x; tile < NTILE32; tile += gridDim.x) {
        __syncthreads();   // smem reuse guard (also orders weight preload)

        int rowA = tile * 32 + rl;
        int rowB = rowA + 16;
        bool vA = rowA < N_NODES;
        bool vB = rowB < N_NODES;

        u64 aA01 = 0, aA23 = 0, aB01 = 0, aB23 = 0;
        if (vA) gather_row(srcu, rowA, t, aA01, aA23);
        if (vB) gather_row(srcu, rowB, t, aB01, aB23);

        if (vA) {
            ulonglong2 e = srcu[(size_t)rowA * 16 + t];
            ulonglong2 s4, p4;
            s4.x = add2(e.x, aA01); s4.y = add2(e.y, aA23);
            p4.x = mul2(e.x, aA01); p4.y = mul2(e.y, aA23);
            *reinterpret_cast<ulonglong2*>(ssh + rl * EMB + 4 * t) = s4;
            *reinterpret_cast<ulonglong2*>(psh + rl * EMB + 4 * t) = p4;
        }
        if (vB) {
            ulonglong2 e = srcu[(size_t)rowB * 16 + t];
            ulonglong2 s4, p4;
            s4.x = add2(e.x, aB01); s4.y = add2(e.y, aB23);
            p4.x = mul2(e.x, aB01); p4.y = mul2(e.y, aB23);
            *reinterpret_cast<ulonglong2*>(ssh + (rl + 16) * EMB + 4 * t) = s4;
            *reinterpret_cast<ulonglong2*>(psh + (rl + 16) * EMB + 4 * t) = p4;
        }
        __syncthreads();

        // GEMV: outputs 4t..4t+3 for rows rl (A) and rl+16 (B), packed pairs.
        u64 oA01 = 0, oA23 = 0, oB01 = 0, oB23 = 0;
        const ulonglong2* sA = reinterpret_cast<const ulonglong2*>(ssh + rl * EMB);
        const ulonglong2* pA = reinterpret_cast<const ulonglong2*>(psh + rl * EMB);
        const ulonglong2* sB = reinterpret_cast<const ulonglong2*>(ssh + (rl + 16) * EMB);
        const ulonglong2* pB = reinterpret_cast<const ulonglong2*>(psh + (rl + 16) * EMB);

#pragma unroll
        for (int i4 = 0; i4 < 16; i4++) {
            ulonglong2 sav = sA[i4], pav = pA[i4];
            ulonglong2 sbv = sB[i4], pbv = pB[i4];
            float2 sa01 = unpack2(sav.x), sa23 = unpack2(sav.y);
            float2 pa01 = unpack2(pav.x), pa23 = unpack2(pav.y);
            float2 sb01 = unpack2(sbv.x), sb23 = unpack2(sbv.y);
            float2 pb01 = unpack2(pbv.x), pb23 = unpack2(pbv.y);

#define GEMV_STEP(u, SA, PA, SB, PB)                                         \
            {                                                                \
                ulonglong2 wa = w1u[(i4 * 4 + u) * 16 + t];                  \
                ulonglong2 wb = w2u[(i4 * 4 + u) * 16 + t];                  \
                u64 sdA = dup2(SA), pdA = dup2(PA);                          \
                u64 sdB = dup2(SB), pdB = dup2(PB);                          \
                oA01 = fma2(sdA, wa.x, oA01); oA23 = fma2(sdA, wa.y, oA23);  \
                oA01 = fma2(pdA, wb.x, oA01); oA23 = fma2(pdA, wb.y, oA23);  \
                oB01 = fma2(sdB, wa.x, oB01); oB23 = fma2(sdB, wa.y, oB23);  \
                oB01 = fma2(pdB, wb.x, oB01); oB23 = fma2(pdB, wb.y, oB23);  \
            }
            GEMV_STEP(0, sa01.x, pa01.x, sb01.x, pb01.x)
            GEMV_STEP(1, sa01.y, pa01.y, sb01.y, pb01.y)
            GEMV_STEP(2, sa23.x, pa23.x, sb23.x, pb23.x)
            GEMV_STEP(3, sa23.y, pa23.y, sb23.y, pb23.y)
#undef GEMV_STEP
        }

        // leaky_relu slope 0.01 (unpack -> repack)
        float2 A01 = unpack2(oA01), A23 = unpack2(oA23);
        float2 B01 = unpack2(oB01), B23 = unpack2(oB23);
        A01.x = A01.x > 0.f ? A01.x : 0.01f * A01.x;
        A01.y = A01.y > 0.f ? A01.y : 0.01f * A01.y;
        A23.x = A23.x > 0.f ? A23.x : 0.01f * A23.x;
        A23.y = A23.y > 0.f ? A23.y : 0.01f * A23.y;
        B01.x = B01.x > 0.f ? B01.x : 0.01f * B01.x;
        B01.y = B01.y > 0.f ? B01.y : 0.01f * B01.y;
        B23.x = B23.x > 0.f ? B23.x : 0.01f * B23.x;
        B23.y = B23.y > 0.f ? B23.y : 0.01f * B23.y;
        u64 lA01 = pack2(A01.x, A01.y), lA23 = pack2(A23.x, A23.y);
        u64 lB01 = pack2(B01.x, B01.y), lB23 = pack2(B23.x, B23.y);

        ulonglong2* sumu = reinterpret_cast<ulonglong2*>(g_sum);
        if (!last) {
            ulonglong2* dstu = reinterpret_cast<ulonglong2*>(dst);
            if (vA) {
                ulonglong2 o; o.x = lA01; o.y = lA23;
                dstu[(size_t)rowA * 16 + t] = o;
                ulonglong2 sm = sumu[(size_t)rowA * 16 + t];
                sm.x = add2(sm.x, lA01); sm.y = add2(sm.y, lA23);
                sumu[(size_t)rowA * 16 + t] = sm;
            }
            if (vB) {
                ulonglong2 o; o.x = lB01; o.y = lB23;
                dstu[(size_t)rowB * 16 + t] = o;
                ulonglong2 sm = sumu[(size_t)rowB * 16 + t];
                sm.x = add2(sm.x, lB01); sm.y = add2(sm.y, lB23);
                sumu[(size_t)rowB * 16 + t] = sm;
            }
        } else {
            ulonglong2* outu = reinterpret_cast<ulonglong2*>(out);
            u64 q = dup2(0.25f);
            if (vA) {
                ulonglong2 sm = sumu[(size_t)rowA * 16 + t];
                ulonglong2 o;
                o.x = mul2(add2(sm.x, lA01), q);
                o.y = mul2(add2(sm.y, lA23), q);
                outu[(size_t)rowA * 16 + t] = o;
            }
            if (vB) {
                ulonglong2 sm = sumu[(size_t)rowB * 16 + t];
                ulonglong2 o;
                o.x = mul2(add2(sm.x, lB01), q);
                o.y = mul2(add2(sm.y, lB23), q);
                outu[(size_t)rowB * 16 + t] = o;
            }
        }
    }
}

// ---------------------------------------------------------------------------
extern "C" void kernel_launch(void* const* d_in, const int* in_sizes, int n_in,
                              void* d_out, int out_size) {
    const float* user = (const float*)d_in[0];
    const float* item = (const float*)d_in[1];
    const float* w1   = (const float*)d_in[2];
    const float* w2   = (const float*)d_in[3];
    const float* vals = (const float*)d_in[4];
    const int*   rows = (const int*)d_in[5];
    const int*   cols = (const int*)d_in[6];
    int nnz = in_sizes[4];
    if (nnz > NNZ_MAX) nnz = NNZ_MAX;

    const int gv = (TOT4 + 255) / 256;
    const int ge = (nnz + 255) / 256;

    init_kernel<<<gv, 256>>>((const float4*)user, (const float4*)item);

    hist_kernel<<<ge, 256>>>(rows, nnz);
    scan1_kernel<<<NSCAN_BLK, 256>>>();
    scan2_kernel<<<1, 1024>>>();
    scan3_kernel<<<NSCAN_BLK, 256>>>(nnz);
    scatter_kernel<<<ge, 256>>>(rows, cols, vals, nnz);

    float4* egoA = nullptr;
    float4* egoB = nullptr;
    cudaGetSymbolAddress((void**)&egoA, g_egoA);
    cudaGetSymbolAddress((void**)&egoB, g_egoB);

    const float4* w1v = (const float4*)w1;
    const float4* w2v = (const float4*)w2;

    fused_layer_kernel<<<FUSED_GRID, 256>>>(egoA, egoB, w1v,        w2v,        0, nullptr);
    fused_layer_kernel<<<FUSED_GRID, 256>>>(egoB, egoA, w1v + 1024, w2v + 1024, 0, nullptr);
    fused_layer_kernel<<<FUSED_GRID, 256>>>(egoA, nullptr, w1v + 2048, w2v + 2048, 1,
                                            (float4*)d_out);
}

// round 13
// speedup vs baseline: 1.7951x; 1.0308x over previous
#include <cuda_runtime.h>

#define USER_NUM 100000
#define ITEM_NUM 50000
#define N_NODES  150000
#define EMB      64
#define TOT      (N_NODES * EMB)
#define TOT4     (TOT / 4)
#define NNZ_MAX  2400000
#define NSCAN_BLK ((N_NODES + 255) / 256)   /* 586 */
#define NTILE32   ((N_NODES + 31) / 32)     /* 4688 */
#define FUSED_GRID 444                      /* 148 SMs x 3 blocks */

typedef unsigned long long u64;

// ---------------- packed f32x2 helpers (FFMA2 et al., PTX-only) ------------
__device__ __forceinline__ u64 fma2(u64 a, u64 b, u64 c) {
    u64 d; asm("fma.rn.f32x2 %0, %1, %2, %3;" : "=l"(d) : "l"(a), "l"(b), "l"(c));
    return d;
}
__device__ __forceinline__ u64 add2(u64 a, u64 b) {
    u64 d; asm("add.rn.f32x2 %0, %1, %2;" : "=l"(d) : "l"(a), "l"(b));
    return d;
}
__device__ __forceinline__ u64 mul2(u64 a, u64 b) {
    u64 d; asm("mul.rn.f32x2 %0, %1, %2;" : "=l"(d) : "l"(a), "l"(b));
    return d;
}
__device__ __forceinline__ u64 dup2(float s) {
    u64 d; asm("mov.b64 %0, {%1, %1};" : "=l"(d) : "f"(s));
    return d;
}
__device__ __forceinline__ u64 pack2(float lo, float hi) {
    u64 d; asm("mov.b64 %0, {%1, %2};" : "=l"(d) : "f"(lo), "f"(hi));
    return d;
}
__device__ __forceinline__ float2 unpack2(u64 v) {
    float2 r; asm("mov.b64 {%0, %1}, %2;" : "=f"(r.x), "=f"(r.y) : "l"(v));
    return r;
}

// Scratch (device globals): ego0 (A), ego1 (B), ego2 (C); ego3 lives in regs.
__device__ float g_egoA[TOT];
__device__ float g_egoB[TOT];
__device__ float g_egoC[TOT];
__device__ int   g_cnt[N_NODES];
__device__ int   g_rowptr[N_NODES + 1];
__device__ int   g_cursor[N_NODES];
__device__ int   g_blksum[NSCAN_BLK];
__device__ int2  g_edge[NNZ_MAX];           // (col, val bits) packed

// ---------------------------------------------------------------------------
// init: egoA = concat(user,item); zero CSR histogram
// ---------------------------------------------------------------------------
__global__ void init_kernel(const float4* __restrict__ user,
                            const float4* __restrict__ item) {
    int i = blockIdx.x * blockDim.x + threadIdx.x;
    if (i < N_NODES) g_cnt[i] = 0;
    if (i >= TOT4) return;
    const int U4 = USER_NUM * EMB / 4;
    float4 v = (i < U4) ? user[i] : item[i - U4];
    reinterpret_cast<float4*>(g_egoA)[i] = v;
}

// ---------------------------------------------------------------------------
// CSR build: histogram -> 2-level scan -> scatter (col,val packed)
// ---------------------------------------------------------------------------
__global__ void hist_kernel(const int* __restrict__ rows, int nnz) {
    int e = blockIdx.x * blockDim.x + threadIdx.x;
    if (e < nnz) atomicAdd(&g_cnt[rows[e]], 1);
}

__global__ void scan1_kernel() {
    __shared__ int sh[256];
    int t = threadIdx.x;
    int sid = blockIdx.x * 256 + t;
    int v = (sid < N_NODES) ? g_cnt[sid] : 0;
    sh[t] = v;
    __syncthreads();
#pragma unroll
    for (int off = 1; off < 256; off <<= 1) {
        int x = (t >= off) ? sh[t - off] : 0;
        __syncthreads();
        sh[t] += x;
        __syncthreads();
    }
    if (sid < N_NODES) g_rowptr[sid] = sh[t] - v;
    if (t == 255) g_blksum[blockIdx.x] = sh[255];
}

__global__ void scan2_kernel() {
    __shared__ int sh[1024];
    int t = threadIdx.x;
    int v = (t < NSCAN_BLK) ? g_blksum[t] : 0;
    sh[t] = v;
    __syncthreads();
#pragma unroll
    for (int off = 1; off < 1024; off <<= 1) {
        int x = (t >= off) ? sh[t - off] : 0;
        __syncthreads();
        sh[t] += x;
        __syncthreads();
    }
    if (t < NSCAN_BLK) g_blksum[t] = sh[t] - v;
}

__global__ void scan3_kernel(int nnz) {
    int sid = blockIdx.x * blockDim.x + threadIdx.x;
    if (sid >= N_NODES) return;
    int rp = g_rowptr[sid] + g_blksum[sid >> 8];
    g_rowptr[sid] = rp;
    g_cursor[sid] = rp;
    if (sid == 0) g_rowptr[N_NODES] = nnz;
}

__global__ void scatter_kernel(const int* __restrict__ rows,
                               const int* __restrict__ cols,
                               const float* __restrict__ vals, int nnz) {
    int e = blockIdx.x * blockDim.x + threadIdx.x;
    if (e >= nnz) return;
    int r = rows[e];
    int pos = atomicAdd(&g_cursor[r], 1);
    g_edge[pos] = make_int2(cols[e], __float_as_int(vals[e]));
}

// ---------------------------------------------------------------------------
// CSR gather for one row's float4 chunk t, packed f32x2 accumulate.
// 8-unrolled: 8 outstanding 16B L2 loads for latency hiding.
// ---------------------------------------------------------------------------
__device__ __forceinline__ void gather_row(const ulonglong2* __restrict__ srcu,
                                           int row, int t, u64& a01, u64& a23) {
    int i  = g_rowptr[row];
    int e0 = g_rowptr[row + 1];
    for (; i + 7 < e0; i += 8) {
        int2 m[8];
        ulonglong2 x[8];
#pragma unroll
        for (int k = 0; k < 8; k++) m[k] = __ldg(g_edge + i + k);
#pragma unroll
        for (int k = 0; k < 8; k++) x[k] = srcu[(size_t)m[k].x * 16 + t];
#pragma unroll
        for (int k = 0; k < 8; k++) {
            u64 v = dup2(__int_as_float(m[k].y));
            a01 = fma2(v, x[k].x, a01);
            a23 = fma2(v, x[k].y, a23);
        }
    }
    for (; i < e0; i++) {
        int2 m = __ldg(g_edge + i);
        ulonglong2 x = srcu[(size_t)m.x * 16 + t];
        u64 v = dup2(__int_as_float(m.y));
        a01 = fma2(v, x.x, a01);
        a23 = fma2(v, x.y, a23);
    }
}

// ---------------------------------------------------------------------------
// Fused layer: persistent blocks, 32-row tiles.
//   agg  = A @ src;  ego' = leaky((src+agg)@W1 + (src*agg)@W2)
//   non-last: dst = ego'
//   last:     out = (egoA + egoB + src + ego') * 0.25   (the 4-layer mean)
// ---------------------------------------------------------------------------
__global__ void __launch_bounds__(256, 3)
fused_layer_kernel(const float4* __restrict__ src,
                   float4* __restrict__ dst,
                   const float4* __restrict__ w1,
                   const float4* __restrict__ w2,
                   int last, float4* __restrict__ out) {
    __shared__ float4 ws1[EMB * 16];         // 16KB
    __shared__ float4 ws2[EMB * 16];         // 16KB
    __shared__ float  ssh[32 * EMB];         // 8KB  (ego+agg)
    __shared__ float  psh[32 * EMB];         // 8KB  (ego*agg)

    for (int i = threadIdx.x; i < EMB * 16; i += 256) {
        ws1[i] = w1[i];
        ws2[i] = w2[i];
    }

    const int t  = threadIdx.x & 15;
    const int rl = threadIdx.x >> 4;

    const ulonglong2* srcu = reinterpret_cast<const ulonglong2*>(src);
    const ulonglong2* w1u  = reinterpret_cast<const ulonglong2*>(ws1);
    const ulonglong2* w2u  = reinterpret_cast<const ulonglong2*>(ws2);

    for (int tile = blockIdx.x; tile < NTILE32; tile += gridDim.x) {
        __syncthreads();   // smem reuse guard (also orders weight preload)

        int rowA = tile * 32 + rl;
        int rowB = rowA + 16;
        bool vA = rowA < N_NODES;
        bool vB = rowB < N_NODES;

        u64 aA01 = 0, aA23 = 0, aB01 = 0, aB23 = 0;
        if (vA) gather_row(srcu, rowA, t, aA01, aA23);
        if (vB) gather_row(srcu, rowB, t, aB01, aB23);

        if (vA) {
            ulonglong2 e = srcu[(size_t)rowA * 16 + t];
            ulonglong2 s4, p4;
            s4.x = add2(e.x, aA01); s4.y = add2(e.y, aA23);
            p4.x = mul2(e.x, aA01); p4.y = mul2(e.y, aA23);
            *reinterpret_cast<ulonglong2*>(ssh + rl * EMB + 4 * t) = s4;
            *reinterpret_cast<ulonglong2*>(psh + rl * EMB + 4 * t) = p4;
        }
        if (vB) {
            ulonglong2 e = srcu[(size_t)rowB * 16 + t];
            ulonglong2 s4, p4;
            s4.x = add2(e.x, aB01); s4.y = add2(e.y, aB23);
            p4.x = mul2(e.x, aB01); p4.y = mul2(e.y, aB23);
            *reinterpret_cast<ulonglong2*>(ssh + (rl + 16) * EMB + 4 * t) = s4;
            *reinterpret_cast<ulonglong2*>(psh + (rl + 16) * EMB + 4 * t) = p4;
        }
        __syncthreads();

        // GEMV: outputs 4t..4t+3 for rows rl (A) and rl+16 (B), packed pairs.
        u64 oA01 = 0, oA23 = 0, oB01 = 0, oB23 = 0;
        const ulonglong2* sA = reinterpret_cast<const ulonglong2*>(ssh + rl * EMB);
        const ulonglong2* pA = reinterpret_cast<const ulonglong2*>(psh + rl * EMB);
        const ulonglong2* sB = reinterpret_cast<const ulonglong2*>(ssh + (rl + 16) * EMB);
        const ulonglong2* pB = reinterpret_cast<const ulonglong2*>(psh + (rl + 16) * EMB);

#pragma unroll
        for (int i4 = 0; i4 < 16; i4++) {
            ulonglong2 sav = sA[i4], pav = pA[i4];
            ulonglong2 sbv = sB[i4], pbv = pB[i4];
            float2 sa01 = unpack2(sav.x), sa23 = unpack2(sav.y);
            float2 pa01 = unpack2(pav.x), pa23 = unpack2(pav.y);
            float2 sb01 = unpack2(sbv.x), sb23 = unpack2(sbv.y);
            float2 pb01 = unpack2(pbv.x), pb23 = unpack2(pbv.y);

#define GEMV_STEP(u, SA, PA, SB, PB)                                         \
            {                                                                \
                ulonglong2 wa = w1u[(i4 * 4 + u) * 16 + t];                  \
                ulonglong2 wb = w2u[(i4 * 4 + u) * 16 + t];                  \
                u64 sdA = dup2(SA), pdA = dup2(PA);                          \
                u64 sdB = dup2(SB), pdB = dup2(PB);                          \
                oA01 = fma2(sdA, wa.x, oA01); oA23 = fma2(sdA, wa.y, oA23);  \
                oA01 = fma2(pdA, wb.x, oA01); oA23 = fma2(pdA, wb.y, oA23);  \
                oB01 = fma2(sdB, wa.x, oB01); oB23 = fma2(sdB, wa.y, oB23);  \
                oB01 = fma2(pdB, wb.x, oB01); oB23 = fma2(pdB, wb.y, oB23);  \
            }
            GEMV_STEP(0, sa01.x, pa01.x, sb01.x, pb01.x)
            GEMV_STEP(1, sa01.y, pa01.y, sb01.y, pb01.y)
            GEMV_STEP(2, sa23.x, pa23.x, sb23.x, pb23.x)
            GEMV_STEP(3, sa23.y, pa23.y, sb23.y, pb23.y)
#undef GEMV_STEP
        }

        // leaky_relu slope 0.01 (unpack -> repack)
        float2 A01 = unpack2(oA01), A23 = unpack2(oA23);
        float2 B01 = unpack2(oB01), B23 = unpack2(oB23);
        A01.x = A01.x > 0.f ? A01.x : 0.01f * A01.x;
        A01.y = A01.y > 0.f ? A01.y : 0.01f * A01.y;
        A23.x = A23.x > 0.f ? A23.x : 0.01f * A23.x;
        A23.y = A23.y > 0.f ? A23.y : 0.01f * A23.y;
        B01.x = B01.x > 0.f ? B01.x : 0.01f * B01.x;
        B01.y = B01.y > 0.f ? B01.y : 0.01f * B01.y;
        B23.x = B23.x > 0.f ? B23.x : 0.01f * B23.x;
        B23.y = B23.y > 0.f ? B23.y : 0.01f * B23.y;
        u64 lA01 = pack2(A01.x, A01.y), lA23 = pack2(A23.x, A23.y);
        u64 lB01 = pack2(B01.x, B01.y), lB23 = pack2(B23.x, B23.y);

        if (!last) {
            ulonglong2* dstu = reinterpret_cast<ulonglong2*>(dst);
            if (vA) {
                ulonglong2 o; o.x = lA01; o.y = lA23;
                dstu[(size_t)rowA * 16 + t] = o;
            }
            if (vB) {
                ulonglong2 o; o.x = lB01; o.y = lB23;
                dstu[(size_t)rowB * 16 + t] = o;
            }
        } else {
            // out = (ego0 + ego1 + ego2 + ego3) * 0.25
            const ulonglong2* e0u = reinterpret_cast<const ulonglong2*>(g_egoA);
            const ulonglong2* e1u = reinterpret_cast<const ulonglong2*>(g_egoB);
            ulonglong2* outu = reinterpret_cast<ulonglong2*>(out);
            u64 q = dup2(0.25f);
            if (vA) {
                size_t idx = (size_t)rowA * 16 + t;
                ulonglong2 v0 = e0u[idx], v1 = e1u[idx], v2 = srcu[idx];
                ulonglong2 o;
                o.x = mul2(add2(add2(v0.x, v1.x), add2(v2.x, lA01)), q);
                o.y = mul2(add2(add2(v0.y, v1.y), add2(v2.y, lA23)), q);
                outu[idx] = o;
            }
            if (vB) {
                size_t idx = (size_t)rowB * 16 + t;
                ulonglong2 v0 = e0u[idx], v1 = e1u[idx], v2 = srcu[idx];
                ulonglong2 o;
                o.x = mul2(add2(add2(v0.x, v1.x), add2(v2.x, lB01)), q);
                o.y = mul2(add2(add2(v0.y, v1.y), add2(v2.y, lB23)), q);
                outu[idx] = o;
            }
        }
    }
}

// ---------------------------------------------------------------------------
extern "C" void kernel_launch(void* const* d_in, const int* in_sizes, int n_in,
                              void* d_out, int out_size) {
    const float* user = (const float*)d_in[0];
    const float* item = (const float*)d_in[1];
    const float* w1   = (const float*)d_in[2];
    const float* w2   = (const float*)d_in[3];
    const float* vals = (const float*)d_in[4];
    const int*   rows = (const int*)d_in[5];
    const int*   cols = (const int*)d_in[6];
    int nnz = in_sizes[4];
    if (nnz > NNZ_MAX) nnz = NNZ_MAX;

    const int gv = (TOT4 + 255) / 256;
    const int ge = (nnz + 255) / 256;

    init_kernel<<<gv, 256>>>((const float4*)user, (const float4*)item);

    hist_kernel<<<ge, 256>>>(rows, nnz);
    scan1_kernel<<<NSCAN_BLK, 256>>>();
    scan2_kernel<<<1, 1024>>>();
    scan3_kernel<<<NSCAN_BLK, 256>>>(nnz);
    scatter_kernel<<<ge, 256>>>(rows, cols, vals, nnz);

    float4* egoA = nullptr;
    float4* egoB = nullptr;
    float4* egoC = nullptr;
    cudaGetSymbolAddress((void**)&egoA, g_egoA);
    cudaGetSymbolAddress((void**)&egoB, g_egoB);
    cudaGetSymbolAddress((void**)&egoC, g_egoC);

    const float4* w1v = (const float4*)w1;
    const float4* w2v = (const float4*)w2;

    // layer 0: A -> B, layer 1: B -> C, layer 2 (last): C (+A,+B) -> out
    fused_layer_kernel<<<FUSED_GRID, 256>>>(egoA, egoB, w1v,        w2v,        0, nullptr);
    fused_layer_kernel<<<FUSED_GRID, 256>>>(egoB, egoC, w1v + 1024, w2v + 1024, 0, nullptr);
    fused_layer_kernel<<<FUSED_GRID, 256>>>(egoC, nullptr, w1v + 2048, w2v + 2048, 1,
                                            (float4*)d_out);
}

// round 14
// speedup vs baseline: 2.0848x; 1.1614x over previous
#include <cuda_runtime.h>

#define USER_NUM 100000
#define ITEM_NUM 50000
#define N_NODES  150000
#define EMB      64
#define TOT      (N_NODES * EMB)
#define TOT4     (TOT / 4)
#define NNZ_MAX  2400000
#define NSCAN_BLK ((N_NODES + 255) / 256)   /* 586 */
#define NTILE64   ((N_NODES + 63) / 64)     /* 2344 */
#define FUSED_GRID 444                      /* 148 SMs x 3 blocks */
#define FUSED_SMEM 65536                    /* 16K ws1 + 16K ws2 + 16K ssh + 16K psh */

typedef unsigned long long u64;

// ---------------- packed f32x2 helpers (FFMA2 et al., PTX-only) ------------
__device__ __forceinline__ u64 fma2(u64 a, u64 b, u64 c) {
    u64 d; asm("fma.rn.f32x2 %0, %1, %2, %3;" : "=l"(d) : "l"(a), "l"(b), "l"(c));
    return d;
}
__device__ __forceinline__ u64 add2(u64 a, u64 b) {
    u64 d; asm("add.rn.f32x2 %0, %1, %2;" : "=l"(d) : "l"(a), "l"(b));
    return d;
}
__device__ __forceinline__ u64 mul2(u64 a, u64 b) {
    u64 d; asm("mul.rn.f32x2 %0, %1, %2;" : "=l"(d) : "l"(a), "l"(b));
    return d;
}
__device__ __forceinline__ u64 dup2(float s) {
    u64 d; asm("mov.b64 %0, {%1, %1};" : "=l"(d) : "f"(s));
    return d;
}
__device__ __forceinline__ u64 pack2(float lo, float hi) {
    u64 d; asm("mov.b64 %0, {%1, %2};" : "=l"(d) : "f"(lo), "f"(hi));
    return d;
}
__device__ __forceinline__ float2 unpack2(u64 v) {
    float2 r; asm("mov.b64 {%0, %1}, %2;" : "=f"(r.x), "=f"(r.y) : "l"(v));
    return r;
}

// Scratch (device globals): ego0 (A), ego1 (B), ego2 (C); ego3 lives in regs.
__device__ float g_egoA[TOT];
__device__ float g_egoB[TOT];
__device__ float g_egoC[TOT];
__device__ int   g_cnt[N_NODES];
__device__ int   g_rowptr[N_NODES + 1];
__device__ int   g_cursor[N_NODES];
__device__ int   g_blksum[NSCAN_BLK];
__device__ int2  g_edge[NNZ_MAX];           // (col, val bits) packed

// ---------------------------------------------------------------------------
// init: egoA = concat(user,item); zero CSR histogram
// ---------------------------------------------------------------------------
__global__ void init_kernel(const float4* __restrict__ user,
                            const float4* __restrict__ item) {
    int i = blockIdx.x * blockDim.x + threadIdx.x;
    if (i < N_NODES) g_cnt[i] = 0;
    if (i >= TOT4) return;
    const int U4 = USER_NUM * EMB / 4;
    float4 v = (i < U4) ? user[i] : item[i - U4];
    reinterpret_cast<float4*>(g_egoA)[i] = v;
}

// ---------------------------------------------------------------------------
// CSR build: histogram -> 2-level scan -> scatter (col,val packed)
// ---------------------------------------------------------------------------
__global__ void hist_kernel(const int* __restrict__ rows, int nnz) {
    int e = blockIdx.x * blockDim.x + threadIdx.x;
    if (e < nnz) atomicAdd(&g_cnt[rows[e]], 1);
}

__global__ void scan1_kernel() {
    __shared__ int sh[256];
    int t = threadIdx.x;
    int sid = blockIdx.x * 256 + t;
    int v = (sid < N_NODES) ? g_cnt[sid] : 0;
    sh[t] = v;
    __syncthreads();
#pragma unroll
    for (int off = 1; off < 256; off <<= 1) {
        int x = (t >= off) ? sh[t - off] : 0;
        __syncthreads();
        sh[t] += x;
        __syncthreads();
    }
    if (sid < N_NODES) g_rowptr[sid] = sh[t] - v;
    if (t == 255) g_blksum[blockIdx.x] = sh[255];
}

__global__ void scan2_kernel() {
    __shared__ int sh[1024];
    int t = threadIdx.x;
    int v = (t < NSCAN_BLK) ? g_blksum[t] : 0;
    sh[t] = v;
    __syncthreads();
#pragma unroll
    for (int off = 1; off < 1024; off <<= 1) {
        int x = (t >= off) ? sh[t - off] : 0;
        __syncthreads();
        sh[t] += x;
        __syncthreads();
    }
    if (t < NSCAN_BLK) g_blksum[t] = sh[t] - v;
}

__global__ void scan3_kernel(int nnz) {
    int sid = blockIdx.x * blockDim.x + threadIdx.x;
    if (sid >= N_NODES) return;
    int rp = g_rowptr[sid] + g_blksum[sid >> 8];
    g_rowptr[sid] = rp;
    g_cursor[sid] = rp;
    if (sid == 0) g_rowptr[N_NODES] = nnz;
}

__global__ void scatter_kernel(const int* __restrict__ rows,
                               const int* __restrict__ cols,
                               const float* __restrict__ vals, int nnz) {
    int e = blockIdx.x * blockDim.x + threadIdx.x;
    if (e >= nnz) return;
    int r = rows[e];
    int pos = atomicAdd(&g_cursor[r], 1);
    g_edge[pos] = make_int2(cols[e], __float_as_int(vals[e]));
}

// ---------------------------------------------------------------------------
// CSR gather for one row's float4 chunk t, packed f32x2 accumulate.
// 8-unrolled: 8 outstanding 16B L2 loads for latency hiding.
// ---------------------------------------------------------------------------
__device__ __forceinline__ void gather_row(const ulonglong2* __restrict__ srcu,
                                           int row, int t, u64& a01, u64& a23) {
    int i  = g_rowptr[row];
    int e0 = g_rowptr[row + 1];
    for (; i + 7 < e0; i += 8) {
        int2 m[8];
        ulonglong2 x[8];
#pragma unroll
        for (int k = 0; k < 8; k++) m[k] = __ldg(g_edge + i + k);
#pragma unroll
        for (int k = 0; k < 8; k++) x[k] = srcu[(size_t)m[k].x * 16 + t];
#pragma unroll
        for (int k = 0; k < 8; k++) {
            u64 v = dup2(__int_as_float(m[k].y));
            a01 = fma2(v, x[k].x, a01);
            a23 = fma2(v, x[k].y, a23);
        }
    }
    for (; i < e0; i++) {
        int2 m = __ldg(g_edge + i);
        ulonglong2 x = srcu[(size_t)m.x * 16 + t];
        u64 v = dup2(__int_as_float(m.y));
        a01 = fma2(v, x.x, a01);
        a23 = fma2(v, x.y, a23);
    }
}

// ---------------------------------------------------------------------------
// Fused layer: persistent blocks, 64-row tiles, 4 rows x 4 cols per thread.
//   agg  = A @ src;  ego' = leaky((src+agg)@W1 + (src*agg)@W2)
//   non-last: dst = ego'
//   last:     out = (egoA + egoB + src + ego') * 0.25   (the 4-layer mean)
// Each weight LDS.128 is reused across 4 rows (halves weight LDS traffic).
// ---------------------------------------------------------------------------
__global__ void __launch_bounds__(256, 3)
fused_layer_kernel(const float4* __restrict__ src,
                   float4* __restrict__ dst,
                   const float4* __restrict__ w1,
                   const float4* __restrict__ w2,
                   int last, float4* __restrict__ out) {
    extern __shared__ char smem_raw[];
    float4* ws1 = reinterpret_cast<float4*>(smem_raw);              // 16KB
    float4* ws2 = reinterpret_cast<float4*>(smem_raw + 16384);      // 16KB
    float*  ssh = reinterpret_cast<float*>(smem_raw + 32768);       // 16KB (ego+agg, 64 rows)
    float*  psh = reinterpret_cast<float*>(smem_raw + 49152);       // 16KB (ego*agg, 64 rows)

    for (int i = threadIdx.x; i < EMB * 16; i += 256) {
        ws1[i] = w1[i];
        ws2[i] = w2[i];
    }

    const int t  = threadIdx.x & 15;    // output cols 4t..4t+3
    const int rq = threadIdx.x >> 4;    // rows rq, rq+16, rq+32, rq+48 of tile

    const ulonglong2* srcu = reinterpret_cast<const ulonglong2*>(src);
    const ulonglong2* w1u  = reinterpret_cast<const ulonglong2*>(ws1);
    const ulonglong2* w2u  = reinterpret_cast<const ulonglong2*>(ws2);

    for (int tile = blockIdx.x; tile < NTILE64; tile += gridDim.x) {
        __syncthreads();   // smem reuse guard (also orders weight preload)

        const int base = tile * 64 + rq;

        // ---- Phase 1: gather 4 rows, stage s = ego+agg, p = ego*agg ----
#pragma unroll
        for (int j = 0; j < 4; j++) {
            int row = base + 16 * j;
            if (row >= N_NODES) continue;
            u64 a01 = 0, a23 = 0;
            gather_row(srcu, row, t, a01, a23);
            ulonglong2 e = srcu[(size_t)row * 16 + t];
            ulonglong2 s4, p4;
            s4.x = add2(e.x, a01); s4.y = add2(e.y, a23);
            p4.x = mul2(e.x, a01); p4.y = mul2(e.y, a23);
            int lr = rq + 16 * j;
            *reinterpret_cast<ulonglong2*>(ssh + lr * EMB + 4 * t) = s4;
            *reinterpret_cast<ulonglong2*>(psh + lr * EMB + 4 * t) = p4;
        }
        __syncthreads();

        // ---- Phase 2: GEMV, 4 rows x 4 cols per thread ----
        u64 o01[4] = {0, 0, 0, 0};
        u64 o23[4] = {0, 0, 0, 0};

#pragma unroll
        for (int i4 = 0; i4 < 16; i4++) {
            // operands: s/p for 4 rows, 4 i-values each
            float sA[4][4], pA[4][4];
#pragma unroll
            for (int j = 0; j < 4; j++) {
                int lr = rq + 16 * j;
                ulonglong2 sv = *reinterpret_cast<const ulonglong2*>(ssh + lr * EMB + 4 * i4);
                ulonglong2 pv = *reinterpret_cast<const ulonglong2*>(psh + lr * EMB + 4 * i4);
                float2 s01 = unpack2(sv.x), s23 = unpack2(sv.y);
                float2 p01 = unpack2(pv.x), p23 = unpack2(pv.y);
                sA[j][0] = s01.x; sA[j][1] = s01.y; sA[j][2] = s23.x; sA[j][3] = s23.y;
                pA[j][0] = p01.x; pA[j][1] = p01.y; pA[j][2] = p23.x; pA[j][3] = p23.y;
            }
#pragma unroll
            for (int u = 0; u < 4; u++) {
                ulonglong2 wa = w1u[(i4 * 4 + u) * 16 + t];
                ulonglong2 wb = w2u[(i4 * 4 + u) * 16 + t];
#pragma unroll
                for (int j = 0; j < 4; j++) {
                    u64 sd = dup2(sA[j][u]);
                    u64 pd = dup2(pA[j][u]);
                    o01[j] = fma2(sd, wa.x, o01[j]);
                    o23[j] = fma2(sd, wa.y, o23[j]);
                    o01[j] = fma2(pd, wb.x, o01[j]);
                    o23[j] = fma2(pd, wb.y, o23[j]);
                }
            }
        }

        // ---- Epilogue: leaky_relu, write ----
#pragma unroll
        for (int j = 0; j < 4; j++) {
            int row = base + 16 * j;
            if (row >= N_NODES) continue;
            float2 A01 = unpack2(o01[j]), A23 = unpack2(o23[j]);
            A01.x = A01.x > 0.f ? A01.x : 0.01f * A01.x;
            A01.y = A01.y > 0.f ? A01.y : 0.01f * A01.y;
            A23.x = A23.x > 0.f ? A23.x : 0.01f * A23.x;
            A23.y = A23.y > 0.f ? A23.y : 0.01f * A23.y;
            u64 l01 = pack2(A01.x, A01.y);
            u64 l23 = pack2(A23.x, A23.y);
            size_t idx = (size_t)row * 16 + t;

            if (!last) {
                ulonglong2 o; o.x = l01; o.y = l23;
                reinterpret_cast<ulonglong2*>(dst)[idx] = o;
            } else {
                const ulonglong2* e0u = reinterpret_cast<const ulonglong2*>(g_egoA);
                const ulonglong2* e1u = reinterpret_cast<const ulonglong2*>(g_egoB);
                u64 q = dup2(0.25f);
                ulonglong2 v0 = e0u[idx], v1 = e1u[idx], v2 = srcu[idx];
                ulonglong2 o;
                o.x = mul2(add2(add2(v0.x, v1.x), add2(v2.x, l01)), q);
                o.y = mul2(add2(add2(v0.y, v1.y), add2(v2.y, l23)), q);
                reinterpret_cast<ulonglong2*>(out)[idx] = o;
            }
        }
    }
}

// ---------------------------------------------------------------------------
extern "C" void kernel_launch(void* const* d_in, const int* in_sizes, int n_in,
                              void* d_out, int out_size) {
    const float* user = (const float*)d_in[0];
    const float* item = (const float*)d_in[1];
    const float* w1   = (const float*)d_in[2];
    const float* w2   = (const float*)d_in[3];
    const float* vals = (const float*)d_in[4];
    const int*   rows = (const int*)d_in[5];
    const int*   cols = (const int*)d_in[6];
    int nnz = in_sizes[4];
    if (nnz > NNZ_MAX) nnz = NNZ_MAX;

    const int gv = (TOT4 + 255) / 256;
    const int ge = (nnz + 255) / 256;

    cudaFuncSetAttribute(fused_layer_kernel,
                         cudaFuncAttributeMaxDynamicSharedMemorySize, FUSED_SMEM);

    init_kernel<<<gv, 256>>>((const float4*)user, (const float4*)item);

    hist_kernel<<<ge, 256>>>(rows, nnz);
    scan1_kernel<<<NSCAN_BLK, 256>>>();
    scan2_kernel<<<1, 1024>>>();
    scan3_kernel<<<NSCAN_BLK, 256>>>(nnz);
    scatter_kernel<<<ge, 256>>>(rows, cols, vals, nnz);

    float4* egoA = nullptr;
    float4* egoB = nullptr;
    float4* egoC = nullptr;
    cudaGetSymbolAddress((void**)&egoA, g_egoA);
    cudaGetSymbolAddress((void**)&egoB, g_egoB);
    cudaGetSymbolAddress((void**)&egoC, g_egoC);

    const float4* w1v = (const float4*)w1;
    const float4* w2v = (const float4*)w2;

    // layer 0: A -> B, layer 1: B -> C, layer 2 (last): C (+A,+B) -> out
    fused_layer_kernel<<<FUSED_GRID, 256, FUSED_SMEM>>>(egoA, egoB, w1v, w2v, 0, nullptr);
    fused_layer_kernel<<<FUSED_GRID, 256, FUSED_SMEM>>>(egoB, egoC, w1v + 1024, w2v + 1024, 0, nullptr);
    fused_layer_kernel<<<FUSED_GRID, 256, FUSED_SMEM>>>(egoC, nullptr, w1v + 2048, w2v + 2048, 1,
                                                        (float4*)d_out);
}